// round 1
// baseline (speedup 1.0000x reference)
#include <cuda_runtime.h>

#define BB 4
#define CC 512
#define CQ 64
#define DD 128   // 2*CQ
#define NN 4096  // H*W

// ---- scratch (module-scope device globals; no allocations allowed) ----
__device__ float g_q[BB * DD * NN];              // 8 MB
__device__ float g_k[BB * DD * NN];              // 8 MB
__device__ float g_v[BB * CC * NN];              // 32 MB
__device__ float g_e[(size_t)BB * NN * NN];      // 256 MB (energy / attn in-place)

// ============================================================================
// Generic 64x64-tile SGEMM family: 16x16 threads, 4x4 micro-tile, KT=16.
// ============================================================================

// Out[b, m_off+m, n] = sum_k W[m,k] * X[b,k,n] + bias[m]      (K = CC = 512)
__global__ void gemm_nn_proj(const float* __restrict__ W,
                             const float* __restrict__ bias,
                             const float* __restrict__ X,
                             float* __restrict__ Out,
                             int outBatchStride, int m_off)
{
    __shared__ float As[16][64];
    __shared__ float Bs[16][64];
    const int b = blockIdx.z;
    const float* Xb = X + (size_t)b * CC * NN;
    float* Ob = Out + (size_t)b * outBatchStride + (size_t)m_off * NN;
    const int m0 = blockIdx.y * 64;
    const int n0 = blockIdx.x * 64;
    const int tx = threadIdx.x, ty = threadIdx.y;
    const int t = ty * 16 + tx;

    const int am = t >> 2;          // 0..63 (row of W tile)
    const int ak = (t & 3) * 4;     // k offset within KT
    const int bk = t >> 4;          // 0..15 (k row of X tile)
    const int bn = (t & 15) * 4;    // n offset

    float acc[4][4] = {};
    for (int kt = 0; kt < CC; kt += 16) {
        float4 av = *(const float4*)&W[(size_t)(m0 + am) * CC + kt + ak];
        As[ak + 0][am] = av.x; As[ak + 1][am] = av.y;
        As[ak + 2][am] = av.z; As[ak + 3][am] = av.w;
        *(float4*)&Bs[bk][bn] =
            *(const float4*)&Xb[(size_t)(kt + bk) * NN + n0 + bn];
        __syncthreads();
#pragma unroll
        for (int k = 0; k < 16; k++) {
            float4 a4 = *(const float4*)&As[k][ty * 4];
            float4 b4 = *(const float4*)&Bs[k][tx * 4];
            float a[4] = {a4.x, a4.y, a4.z, a4.w};
            float bb[4] = {b4.x, b4.y, b4.z, b4.w};
#pragma unroll
            for (int i = 0; i < 4; i++)
#pragma unroll
                for (int j = 0; j < 4; j++)
                    acc[i][j] += a[i] * bb[j];
        }
        __syncthreads();
    }
#pragma unroll
    for (int i = 0; i < 4; i++) {
        const int m = m0 + ty * 4 + i;
        const float bi = bias[m];
#pragma unroll
        for (int j = 0; j < 4; j++)
            Ob[(size_t)m * NN + n0 + tx * 4 + j] = acc[i][j] + bi;
    }
}

// E[b,i,j] = sum_d Q[b,d,i] * K[b,d,j]   (TN: both operands d-major, K = DD)
__global__ void gemm_tn_energy(const float* __restrict__ Q,
                               const float* __restrict__ Km,
                               float* __restrict__ E)
{
    __shared__ float As[16][64];
    __shared__ float Bs[16][64];
    const int b = blockIdx.z;
    const float* Qb = Q + (size_t)b * DD * NN;
    const float* Kb = Km + (size_t)b * DD * NN;
    float* Eb = E + (size_t)b * NN * NN;
    const int i0 = blockIdx.y * 64;
    const int j0 = blockIdx.x * 64;
    const int tx = threadIdx.x, ty = threadIdx.y;
    const int t = ty * 16 + tx;

    const int lk = t >> 4;          // 0..15
    const int lc = (t & 15) * 4;    // 0..60

    float acc[4][4] = {};
    for (int kt = 0; kt < DD; kt += 16) {
        *(float4*)&As[lk][lc] =
            *(const float4*)&Qb[(size_t)(kt + lk) * NN + i0 + lc];
        *(float4*)&Bs[lk][lc] =
            *(const float4*)&Kb[(size_t)(kt + lk) * NN + j0 + lc];
        __syncthreads();
#pragma unroll
        for (int k = 0; k < 16; k++) {
            float4 a4 = *(const float4*)&As[k][ty * 4];
            float4 b4 = *(const float4*)&Bs[k][tx * 4];
            float a[4] = {a4.x, a4.y, a4.z, a4.w};
            float bb[4] = {b4.x, b4.y, b4.z, b4.w};
#pragma unroll
            for (int i = 0; i < 4; i++)
#pragma unroll
                for (int j = 0; j < 4; j++)
                    acc[i][j] += a[i] * bb[j];
        }
        __syncthreads();
    }
#pragma unroll
    for (int i = 0; i < 4; i++)
#pragma unroll
        for (int j = 0; j < 4; j++)
            Eb[(size_t)(i0 + ty * 4 + i) * NN + j0 + tx * 4 + j] = acc[i][j];
}

// Row softmax over j: E[row, :], row = b*NN + i, in place.
__global__ void softmax_rows(float* __restrict__ E)
{
    __shared__ float red[256];
    const size_t base = (size_t)blockIdx.x * NN;
    const int tid = threadIdx.x;

    float m = -1e30f;
    for (int j = tid; j < NN; j += 256) m = fmaxf(m, E[base + j]);
    red[tid] = m;
    __syncthreads();
    for (int s = 128; s > 0; s >>= 1) {
        if (tid < s) red[tid] = fmaxf(red[tid], red[tid + s]);
        __syncthreads();
    }
    m = red[0];
    __syncthreads();

    float sum = 0.f;
    for (int j = tid; j < NN; j += 256) {
        float e = __expf(E[base + j] - m);
        E[base + j] = e;
        sum += e;
    }
    red[tid] = sum;
    __syncthreads();
    for (int s = 128; s > 0; s >>= 1) {
        if (tid < s) red[tid] += red[tid + s];
        __syncthreads();
    }
    const float inv = 1.0f / red[0];
    __syncthreads();

    for (int j = tid; j < NN; j += 256) E[base + j] *= inv;
}

// Out[b,c,i] = gamma * sum_j V[b,c,j]*A[b,i,j] + X[b,c,i]   (NT, K = NN)
__global__ void gemm_nt_out(const float* __restrict__ V,
                            const float* __restrict__ A,
                            const float* __restrict__ X,
                            const float* __restrict__ gamma,
                            float* __restrict__ Out)
{
    __shared__ float As[16][64];
    __shared__ float Bs[16][64];
    const int b = blockIdx.z;
    const float* Vb = V + (size_t)b * CC * NN;
    const float* Ab = A + (size_t)b * NN * NN;
    const int m0 = blockIdx.y * 64;   // channel c
    const int n0 = blockIdx.x * 64;   // position i
    const int tx = threadIdx.x, ty = threadIdx.y;
    const int t = ty * 16 + tx;

    const int lr = t >> 2;          // 0..63 (row of tile)
    const int lk = (t & 3) * 4;     // k offset

    float acc[4][4] = {};
    for (int kt = 0; kt < NN; kt += 16) {
        float4 av = *(const float4*)&Vb[(size_t)(m0 + lr) * NN + kt + lk];
        As[lk + 0][lr] = av.x; As[lk + 1][lr] = av.y;
        As[lk + 2][lr] = av.z; As[lk + 3][lr] = av.w;
        float4 bv = *(const float4*)&Ab[(size_t)(n0 + lr) * NN + kt + lk];
        Bs[lk + 0][lr] = bv.x; Bs[lk + 1][lr] = bv.y;
        Bs[lk + 2][lr] = bv.z; Bs[lk + 3][lr] = bv.w;
        __syncthreads();
#pragma unroll
        for (int k = 0; k < 16; k++) {
            float4 a4 = *(const float4*)&As[k][ty * 4];
            float4 b4 = *(const float4*)&Bs[k][tx * 4];
            float a[4] = {a4.x, a4.y, a4.z, a4.w};
            float bb[4] = {b4.x, b4.y, b4.z, b4.w};
#pragma unroll
            for (int i = 0; i < 4; i++)
#pragma unroll
                for (int j = 0; j < 4; j++)
                    acc[i][j] += a[i] * bb[j];
        }
        __syncthreads();
    }
    const float g = __ldg(gamma);
#pragma unroll
    for (int i = 0; i < 4; i++) {
        const int c = m0 + ty * 4 + i;
#pragma unroll
        for (int j = 0; j < 4; j++) {
            const size_t idx = (size_t)b * CC * NN + (size_t)c * NN + n0 + tx * 4 + j;
            Out[idx] = g * acc[i][j] + X[idx];
        }
    }
}

// ============================================================================

extern "C" void kernel_launch(void* const* d_in, const int* in_sizes, int n_in,
                              void* d_out, int out_size)
{
    const float* x     = (const float*)d_in[0];
    const float* dep   = (const float*)d_in[1];
    const float* wq    = (const float*)d_in[2];
    const float* bq    = (const float*)d_in[3];
    const float* wqd   = (const float*)d_in[4];
    const float* bqd   = (const float*)d_in[5];
    const float* wk    = (const float*)d_in[6];
    const float* bk    = (const float*)d_in[7];
    const float* wkd   = (const float*)d_in[8];
    const float* bkd   = (const float*)d_in[9];
    const float* wv    = (const float*)d_in[10];
    const float* bv    = (const float*)d_in[11];
    const float* gamma = (const float*)d_in[12];
    float* out = (float*)d_out;

    float *q, *k, *v, *e;
    cudaGetSymbolAddress((void**)&q, g_q);
    cudaGetSymbolAddress((void**)&k, g_k);
    cudaGetSymbolAddress((void**)&v, g_v);
    cudaGetSymbolAddress((void**)&e, g_e);

    dim3 thr(16, 16);

    // q / k projections (M = 64 each half) and v projection (M = 512)
    dim3 gqk(NN / 64, 1, BB);
    gemm_nn_proj<<<gqk, thr>>>(wq,  bq,  x,   q, DD * NN, 0);
    gemm_nn_proj<<<gqk, thr>>>(wqd, bqd, dep, q, DD * NN, CQ);
    gemm_nn_proj<<<gqk, thr>>>(wk,  bk,  x,   k, DD * NN, 0);
    gemm_nn_proj<<<gqk, thr>>>(wkd, bkd, dep, k, DD * NN, CQ);
    dim3 gv(NN / 64, CC / 64, BB);
    gemm_nn_proj<<<gv, thr>>>(wv, bv, x, v, CC * NN, 0);

    // energy = q^T k  -> [B, N, N]
    dim3 ge(NN / 64, NN / 64, BB);
    gemm_tn_energy<<<ge, thr>>>(q, k, e);

    // softmax over last axis, in place
    softmax_rows<<<BB * NN, 256>>>(e);

    // out = gamma * (v @ attn^T) + x
    dim3 go(NN / 64, CC / 64, BB);
    gemm_nt_out<<<go, thr>>>(v, e, x, gamma, out);
}

// round 3
// speedup vs baseline: 1.3398x; 1.3398x over previous
#include <cuda_runtime.h>

#define BB 4
#define CC 512
#define CQ 64
#define DD 128   // 2*CQ
#define NN 4096  // H*W

// ---- scratch (device globals; no allocations allowed) ----
__device__ float g_q[BB * DD * NN];              // 8 MB   [B][D][N]
__device__ float g_k[BB * DD * NN];              // 8 MB
__device__ float g_v[BB * CC * NN];              // 32 MB  [B][C][N]
__device__ float g_e[(size_t)BB * NN * NN];      // 256 MB (energy / exp in place)
__device__ float g_s[BB * NN];                   // 1/rowsum

// ============================================================================
// Shared 128x128x16 compute step: 256 threads, 8x8 micro-tile.
// As/Bs layout: [k][m] and [k][n], 16 x 128 floats each.
// ============================================================================
__device__ __forceinline__ void mm_step(const float* __restrict__ As,
                                        const float* __restrict__ Bs,
                                        int tx, int ty, float acc[8][8])
{
#pragma unroll
    for (int kk = 0; kk < 16; kk++) {
        float a[8], b[8];
        *(float4*)&a[0] = *(const float4*)&As[kk * 128 + ty * 4];
        *(float4*)&a[4] = *(const float4*)&As[kk * 128 + 64 + ty * 4];
        *(float4*)&b[0] = *(const float4*)&Bs[kk * 128 + tx * 4];
        *(float4*)&b[4] = *(const float4*)&Bs[kk * 128 + 64 + tx * 4];
#pragma unroll
        for (int i = 0; i < 8; i++)
#pragma unroll
            for (int j = 0; j < 8; j++)
                acc[i][j] += a[i] * b[j];
    }
}

// ============================================================================
// NN proj GEMM: Out[b, m, n] = sum_k W[m,k] * X[b,k,n] + bias[m]
// ============================================================================
__global__ void __launch_bounds__(256, 2)
gemm_nn(const float* __restrict__ W, const float* __restrict__ bias,
        const float* __restrict__ X, float* __restrict__ Out)
{
    __shared__ float As[2][16 * 128], Bs[2][16 * 128];
    const int b = blockIdx.z;
    const float* Xb = X + (size_t)b * CC * NN;
    float* Ob = Out + (size_t)b * CC * NN;
    const int m0 = blockIdx.y * 128;
    const int n0 = blockIdx.x * 128;
    const int t = threadIdx.x;
    const int tx = t & 15, ty = t >> 4;

    const int aM = t & 127, aK = (t >> 7) * 8;     // A: 8 k-contig floats
    const int bK = t >> 4,  bN = (t & 15) * 8;     // B: 8 n-contig floats

    float4 ra0, ra1, rb0, rb1;
    float acc[8][8] = {};

    auto ldg = [&](int kt) {
        const float* pa = &W[(size_t)(m0 + aM) * CC + kt + aK];
        ra0 = *(const float4*)pa; ra1 = *(const float4*)(pa + 4);
        const float* pb = &Xb[(size_t)(kt + bK) * NN + n0 + bN];
        rb0 = *(const float4*)pb; rb1 = *(const float4*)(pb + 4);
    };
    auto sts = [&](int buf) {
        float* a = As[buf];
        a[(aK + 0) * 128 + aM] = ra0.x; a[(aK + 1) * 128 + aM] = ra0.y;
        a[(aK + 2) * 128 + aM] = ra0.z; a[(aK + 3) * 128 + aM] = ra0.w;
        a[(aK + 4) * 128 + aM] = ra1.x; a[(aK + 5) * 128 + aM] = ra1.y;
        a[(aK + 6) * 128 + aM] = ra1.z; a[(aK + 7) * 128 + aM] = ra1.w;
        float* bb = Bs[buf];
        *(float4*)&bb[bK * 128 + bN] = rb0;
        *(float4*)&bb[bK * 128 + bN + 4] = rb1;
    };

    ldg(0); sts(0); __syncthreads();
    int buf = 0;
    for (int kt = 0; kt < CC; kt += 16) {
        const bool more = (kt + 16) < CC;
        if (more) ldg(kt + 16);
        mm_step(As[buf], Bs[buf], tx, ty, acc);
        if (more) { sts(buf ^ 1); __syncthreads(); buf ^= 1; }
    }

#pragma unroll
    for (int i = 0; i < 8; i++) {
        const int m = m0 + ((i < 4) ? ty * 4 + i : 64 + ty * 4 + i - 4);
        const float bi = bias[m];
        float4 o;
        o.x = acc[i][0] + bi; o.y = acc[i][1] + bi;
        o.z = acc[i][2] + bi; o.w = acc[i][3] + bi;
        *(float4*)&Ob[(size_t)m * NN + n0 + tx * 4] = o;
        o.x = acc[i][4] + bi; o.y = acc[i][5] + bi;
        o.z = acc[i][6] + bi; o.w = acc[i][7] + bi;
        *(float4*)&Ob[(size_t)m * NN + n0 + 64 + tx * 4] = o;
    }
}

// ============================================================================
// Dual proj: rows 0-63 use W0 -> Out0 (q), rows 64-127 use W1 -> Out1 (k).
// ============================================================================
__global__ void __launch_bounds__(256, 2)
gemm_nn_dual(const float* __restrict__ W0, const float* __restrict__ W1,
             const float* __restrict__ bias0, const float* __restrict__ bias1,
             const float* __restrict__ X,
             float* __restrict__ Out0, float* __restrict__ Out1)
{
    __shared__ float As[2][16 * 128], Bs[2][16 * 128];
    const int b = blockIdx.z;
    const float* Xb = X + (size_t)b * CC * NN;
    const int n0 = blockIdx.x * 128;
    const int t = threadIdx.x;
    const int tx = t & 15, ty = t >> 4;

    const int aM = t & 127, aK = (t >> 7) * 8;
    const int bK = t >> 4,  bN = (t & 15) * 8;
    const float* Wrow = (aM < CQ) ? (W0 + (size_t)aM * CC)
                                  : (W1 + (size_t)(aM - CQ) * CC);

    float4 ra0, ra1, rb0, rb1;
    float acc[8][8] = {};

    auto ldg = [&](int kt) {
        const float* pa = Wrow + kt + aK;
        ra0 = *(const float4*)pa; ra1 = *(const float4*)(pa + 4);
        const float* pb = &Xb[(size_t)(kt + bK) * NN + n0 + bN];
        rb0 = *(const float4*)pb; rb1 = *(const float4*)(pb + 4);
    };
    auto sts = [&](int buf) {
        float* a = As[buf];
        a[(aK + 0) * 128 + aM] = ra0.x; a[(aK + 1) * 128 + aM] = ra0.y;
        a[(aK + 2) * 128 + aM] = ra0.z; a[(aK + 3) * 128 + aM] = ra0.w;
        a[(aK + 4) * 128 + aM] = ra1.x; a[(aK + 5) * 128 + aM] = ra1.y;
        a[(aK + 6) * 128 + aM] = ra1.z; a[(aK + 7) * 128 + aM] = ra1.w;
        float* bb = Bs[buf];
        *(float4*)&bb[bK * 128 + bN] = rb0;
        *(float4*)&bb[bK * 128 + bN + 4] = rb1;
    };

    ldg(0); sts(0); __syncthreads();
    int buf = 0;
    for (int kt = 0; kt < CC; kt += 16) {
        const bool more = (kt + 16) < CC;
        if (more) ldg(kt + 16);
        mm_step(As[buf], Bs[buf], tx, ty, acc);
        if (more) { sts(buf ^ 1); __syncthreads(); buf ^= 1; }
    }

#pragma unroll
    for (int i = 0; i < 8; i++) {
        const int m = (i < 4) ? ty * 4 + i : 64 + ty * 4 + i - 4;   // <64 => q, else k
        float* dst;
        float bi;
        if (m < CQ) { dst = Out0 + (size_t)b * DD * NN + (size_t)m * NN;        bi = bias0[m]; }
        else        { dst = Out1 + (size_t)b * DD * NN + (size_t)(m - CQ) * NN; bi = bias1[m - CQ]; }
        float4 o;
        o.x = acc[i][0] + bi; o.y = acc[i][1] + bi;
        o.z = acc[i][2] + bi; o.w = acc[i][3] + bi;
        *(float4*)&dst[n0 + tx * 4] = o;
        o.x = acc[i][4] + bi; o.y = acc[i][5] + bi;
        o.z = acc[i][6] + bi; o.w = acc[i][7] + bi;
        *(float4*)&dst[n0 + 64 + tx * 4] = o;
    }
}

// ============================================================================
// Energy TN: E[b,i,j] = sum_d Q[b,d,i] * K[b,d,j].
// ============================================================================
__global__ void __launch_bounds__(256, 2)
gemm_tn_energy(const float* __restrict__ Q, const float* __restrict__ Km,
               float* __restrict__ E)
{
    __shared__ float As[2][16 * 128], Bs[2][16 * 128];
    const int b = blockIdx.z;
    const float* Qb = Q + (size_t)b * DD * NN;
    const float* Kb = Km + (size_t)b * DD * NN;
    float* Eb = E + (size_t)b * NN * NN;
    const int i0 = blockIdx.y * 128;
    const int j0 = blockIdx.x * 128;
    const int t = threadIdx.x;
    const int tx = t & 15, ty = t >> 4;

    const int lK = t >> 4, lM = (t & 15) * 8;   // direct [k][m] float4 loads

    float4 ra0, ra1, rb0, rb1;
    float acc[8][8] = {};

    auto ldg = [&](int kt) {
        const float* pa = &Qb[(size_t)(kt + lK) * NN + i0 + lM];
        ra0 = *(const float4*)pa; ra1 = *(const float4*)(pa + 4);
        const float* pb = &Kb[(size_t)(kt + lK) * NN + j0 + lM];
        rb0 = *(const float4*)pb; rb1 = *(const float4*)(pb + 4);
    };
    auto sts = [&](int buf) {
        *(float4*)&As[buf][lK * 128 + lM] = ra0;
        *(float4*)&As[buf][lK * 128 + lM + 4] = ra1;
        *(float4*)&Bs[buf][lK * 128 + lM] = rb0;
        *(float4*)&Bs[buf][lK * 128 + lM + 4] = rb1;
    };

    ldg(0); sts(0); __syncthreads();
    int buf = 0;
    for (int kt = 0; kt < DD; kt += 16) {
        const bool more = (kt + 16) < DD;
        if (more) ldg(kt + 16);
        mm_step(As[buf], Bs[buf], tx, ty, acc);
        if (more) { sts(buf ^ 1); __syncthreads(); buf ^= 1; }
    }

#pragma unroll
    for (int i = 0; i < 8; i++) {
        const int row = i0 + ((i < 4) ? ty * 4 + i : 64 + ty * 4 + i - 4);
        *(float4*)&Eb[(size_t)row * NN + j0 + tx * 4] = *(float4*)&acc[i][0];
        *(float4*)&Eb[(size_t)row * NN + j0 + 64 + tx * 4] = *(float4*)&acc[i][4];
    }
}

// ============================================================================
// Softmax (one block per row, single pass in registers):
// writes unnormalized exp(e - max) in place, 1/rowsum to invs.
// Row = 1024 float4; 256 threads x 4 chunks, stride 256 (FIXED).
// ============================================================================
__global__ void __launch_bounds__(256)
softmax_rows(float* __restrict__ E, float* __restrict__ invs)
{
    __shared__ float red[8];
    float4* E4 = (float4*)E;
    const size_t base4 = (size_t)blockIdx.x * (NN / 4);
    const int tid = threadIdx.x;
    const int lane = tid & 31, wid = tid >> 5;

    float4 v[4];
#pragma unroll
    for (int u = 0; u < 4; u++) v[u] = E4[base4 + u * 256 + tid];

    float m = -1e30f;
#pragma unroll
    for (int u = 0; u < 4; u++)
        m = fmaxf(m, fmaxf(fmaxf(v[u].x, v[u].y), fmaxf(v[u].z, v[u].w)));
#pragma unroll
    for (int off = 16; off > 0; off >>= 1)
        m = fmaxf(m, __shfl_xor_sync(0xffffffffu, m, off));
    if (lane == 0) red[wid] = m;
    __syncthreads();
    m = red[0];
#pragma unroll
    for (int w = 1; w < 8; w++) m = fmaxf(m, red[w]);
    __syncthreads();

    float s = 0.f;
#pragma unroll
    for (int u = 0; u < 4; u++) {
        v[u].x = __expf(v[u].x - m); v[u].y = __expf(v[u].y - m);
        v[u].z = __expf(v[u].z - m); v[u].w = __expf(v[u].w - m);
        s += v[u].x + v[u].y + v[u].z + v[u].w;
    }
#pragma unroll
    for (int off = 16; off > 0; off >>= 1)
        s += __shfl_xor_sync(0xffffffffu, s, off);
    if (lane == 0) red[wid] = s;
    __syncthreads();
    s = red[0];
#pragma unroll
    for (int w = 1; w < 8; w++) s += red[w];

#pragma unroll
    for (int u = 0; u < 4; u++) E4[base4 + u * 256 + tid] = v[u];
    if (tid == 0) invs[blockIdx.x] = 1.0f / s;
}

// ============================================================================
// Out NT: out[b,c,i] = gamma * (sum_j V[b,c,j]*P[b,i,j]) * inv[b,i] + X[b,c,i]
// ============================================================================
__global__ void __launch_bounds__(256, 2)
gemm_nt_out(const float* __restrict__ V, const float* __restrict__ P,
            const float* __restrict__ X, const float* __restrict__ gamma,
            const float* __restrict__ invs, float* __restrict__ Out)
{
    __shared__ float As[2][16 * 128], Bs[2][16 * 128];
    const int b = blockIdx.z;
    const float* Vb = V + (size_t)b * CC * NN;
    const float* Pb = P + (size_t)b * NN * NN;
    const int m0 = blockIdx.x * 128;   // channel c
    const int n0 = blockIdx.y * 128;   // position i
    const int t = threadIdx.x;
    const int tx = t & 15, ty = t >> 4;

    const int aM = t & 127, aK = (t >> 7) * 8;   // both transposed STS
    const int bN = t & 127, bK = (t >> 7) * 8;

    float4 ra0, ra1, rb0, rb1;
    float acc[8][8] = {};

    auto ldg = [&](int kt) {
        const float* pa = &Vb[(size_t)(m0 + aM) * NN + kt + aK];
        ra0 = *(const float4*)pa; ra1 = *(const float4*)(pa + 4);
        const float* pb = &Pb[(size_t)(n0 + bN) * NN + kt + bK];
        rb0 = *(const float4*)pb; rb1 = *(const float4*)(pb + 4);
    };
    auto sts = [&](int buf) {
        float* a = As[buf];
        a[(aK + 0) * 128 + aM] = ra0.x; a[(aK + 1) * 128 + aM] = ra0.y;
        a[(aK + 2) * 128 + aM] = ra0.z; a[(aK + 3) * 128 + aM] = ra0.w;
        a[(aK + 4) * 128 + aM] = ra1.x; a[(aK + 5) * 128 + aM] = ra1.y;
        a[(aK + 6) * 128 + aM] = ra1.z; a[(aK + 7) * 128 + aM] = ra1.w;
        float* bb = Bs[buf];
        bb[(bK + 0) * 128 + bN] = rb0.x; bb[(bK + 1) * 128 + bN] = rb0.y;
        bb[(bK + 2) * 128 + bN] = rb0.z; bb[(bK + 3) * 128 + bN] = rb0.w;
        bb[(bK + 4) * 128 + bN] = rb1.x; bb[(bK + 5) * 128 + bN] = rb1.y;
        bb[(bK + 6) * 128 + bN] = rb1.z; bb[(bK + 7) * 128 + bN] = rb1.w;
    };

    ldg(0); sts(0); __syncthreads();
    int buf = 0;
    for (int kt = 0; kt < NN; kt += 16) {
        const bool more = (kt + 16) < NN;
        if (more) ldg(kt + 16);
        mm_step(As[buf], Bs[buf], tx, ty, acc);
        if (more) { sts(buf ^ 1); __syncthreads(); buf ^= 1; }
    }

    const float g = __ldg(gamma);
    const float4 iv0 = *(const float4*)&invs[b * NN + n0 + tx * 4];
    const float4 iv1 = *(const float4*)&invs[b * NN + n0 + 64 + tx * 4];
#pragma unroll
    for (int i = 0; i < 8; i++) {
        const int c = m0 + ((i < 4) ? ty * 4 + i : 64 + ty * 4 + i - 4);
        const size_t rowBase = (size_t)b * CC * NN + (size_t)c * NN;
        float4 x0 = *(const float4*)&X[rowBase + n0 + tx * 4];
        float4 o0;
        o0.x = g * acc[i][0] * iv0.x + x0.x;
        o0.y = g * acc[i][1] * iv0.y + x0.y;
        o0.z = g * acc[i][2] * iv0.z + x0.z;
        o0.w = g * acc[i][3] * iv0.w + x0.w;
        *(float4*)&Out[rowBase + n0 + tx * 4] = o0;
        float4 x1 = *(const float4*)&X[rowBase + n0 + 64 + tx * 4];
        float4 o1;
        o1.x = g * acc[i][4] * iv1.x + x1.x;
        o1.y = g * acc[i][5] * iv1.y + x1.y;
        o1.z = g * acc[i][6] * iv1.z + x1.z;
        o1.w = g * acc[i][7] * iv1.w + x1.w;
        *(float4*)&Out[rowBase + n0 + 64 + tx * 4] = o1;
    }
}

// ============================================================================

extern "C" void kernel_launch(void* const* d_in, const int* in_sizes, int n_in,
                              void* d_out, int out_size)
{
    const float* x     = (const float*)d_in[0];
    const float* dep   = (const float*)d_in[1];
    const float* wq    = (const float*)d_in[2];
    const float* bq    = (const float*)d_in[3];
    const float* wqd   = (const float*)d_in[4];
    const float* bqd   = (const float*)d_in[5];
    const float* wk    = (const float*)d_in[6];
    const float* bk    = (const float*)d_in[7];
    const float* wkd   = (const float*)d_in[8];
    const float* bkd   = (const float*)d_in[9];
    const float* wv    = (const float*)d_in[10];
    const float* bv    = (const float*)d_in[11];
    const float* gamma = (const float*)d_in[12];
    float* out = (float*)d_out;

    float *q, *k, *v, *e, *s;
    cudaGetSymbolAddress((void**)&q, g_q);
    cudaGetSymbolAddress((void**)&k, g_k);
    cudaGetSymbolAddress((void**)&v, g_v);
    cudaGetSymbolAddress((void**)&e, g_e);
    cudaGetSymbolAddress((void**)&s, g_s);

    // q/k projections: x -> halves [0:64), dep -> halves [64:128)
    gemm_nn_dual<<<dim3(NN / 128, 1, BB), 256>>>(wq,  wk,  bq,  bk,  x,   q,            k);
    gemm_nn_dual<<<dim3(NN / 128, 1, BB), 256>>>(wqd, wkd, bqd, bkd, dep, q + CQ * NN,  k + CQ * NN);

    // v projection
    gemm_nn<<<dim3(NN / 128, CC / 128, BB), 256>>>(wv, bv, x, v);

    // energy = q^T k
    gemm_tn_energy<<<dim3(NN / 128, NN / 128, BB), 256>>>(q, k, e);

    // softmax -> unnormalized exp + 1/rowsum
    softmax_rows<<<BB * NN, 256>>>(e, s);

    // out = gamma * (v @ attn^T) + x   (normalization folded in)
    gemm_nt_out<<<dim3(CC / 128, NN / 128, BB), 256>>>(v, e, x, gamma, s, out);
}

// round 6
// speedup vs baseline: 2.6234x; 1.9580x over previous
#include <cuda_runtime.h>
#include <cuda_bf16.h>
#include <cstdint>

#define BB 4
#define CC 512
#define CQ 64
#define DD 128   // 2*CQ
#define NN 4096  // H*W

// ---------------- scratch (device globals; no allocations allowed) ----------
__device__ __align__(256) __nv_bfloat16 g_qhi[BB * NN * DD];   // [b][i][d]
__device__ __align__(256) __nv_bfloat16 g_qlo[BB * NN * DD];
__device__ __align__(256) __nv_bfloat16 g_khi[BB * NN * DD];   // [b][j][d]
__device__ __align__(256) __nv_bfloat16 g_klo[BB * NN * DD];
__device__ __align__(256) __nv_bfloat16 g_vhi[BB * CC * NN];   // [b][c][n]
__device__ __align__(256) __nv_bfloat16 g_vlo[BB * CC * NN];
__device__ __align__(256) float g_e[(size_t)BB * NN * NN];     // energy fp32
__device__ __align__(256) __nv_bfloat16 g_phi[(size_t)BB * NN * NN];  // exp hi
__device__ __align__(256) __nv_bfloat16 g_plo[(size_t)BB * NN * NN];  // exp lo
__device__ __align__(256) float g_s[BB * NN];                  // 1/rowsum

// ---------------- low-level helpers -----------------------------------------
__device__ __forceinline__ uint32_t smem_to_u32(const void* p) {
    uint32_t a;
    asm("{ .reg .u64 t; cvta.to.shared.u64 t, %1; cvt.u32.u64 %0, t; }" : "=r"(a) : "l"(p));
    return a;
}
#define SWZ(off) ((off) ^ (((off) >> 3) & 0x70))

__device__ __forceinline__ void cp16(uint32_t dst, const void* src) {
    asm volatile("cp.async.cg.shared.global [%0], [%1], 16;" :: "r"(dst), "l"(src));
}
__device__ __forceinline__ void cp_commit() {
    asm volatile("cp.async.commit_group;" ::: "memory");
}
__device__ __forceinline__ void ldsm4(uint32_t r[4], uint32_t addr) {
    asm volatile("ldmatrix.sync.aligned.m8n8.x4.shared.b16 {%0,%1,%2,%3}, [%4];"
                 : "=r"(r[0]), "=r"(r[1]), "=r"(r[2]), "=r"(r[3]) : "r"(addr));
}
__device__ __forceinline__ void mma_bf16(float acc[4], const uint32_t a[4],
                                         uint32_t b0, uint32_t b1) {
    asm volatile("mma.sync.aligned.m16n8k16.row.col.f32.bf16.bf16.f32 "
                 "{%0,%1,%2,%3}, {%4,%5,%6,%7}, {%8,%9}, {%0,%1,%2,%3};"
                 : "+f"(acc[0]), "+f"(acc[1]), "+f"(acc[2]), "+f"(acc[3])
                 : "r"(a[0]), "r"(a[1]), "r"(a[2]), "r"(a[3]), "r"(b0), "r"(b1));
}
__device__ __forceinline__ void split4(const float f[4], __nv_bfloat16 h[4], __nv_bfloat16 l[4])
{
#pragma unroll
    for (int i = 0; i < 4; i++) {
        h[i] = __float2bfloat16(f[i]);
        l[i] = __float2bfloat16(f[i] - __bfloat162float(h[i]));
    }
}

// ---------------- split-bf16 MMA machinery ----------------------------------
// Stage layout in dynamic smem (per stage 64KB, 2 stages = 128KB):
//   +0      A_hi 128x64 bf16 (128B swizzled rows)
//   +16384  A_lo
//   +32768  B_hi
//   +49152  B_lo
#define STG 65536
#define MMA_SMEM_BYTES (2 * STG)

// Fill one stage: 16 cp.async per thread (4 per tile).
__device__ __forceinline__ void stage_load(
    const __nv_bfloat16* __restrict__ Ahi, const __nv_bfloat16* __restrict__ Alo,
    size_t aStr,
    const __nv_bfloat16* __restrict__ Bhi, const __nv_bfloat16* __restrict__ Blo,
    size_t bStr, int kt, uint32_t stageU32, int t)
{
#pragma unroll
    for (int i = 0; i < 4; i++) {
        const int id = t + i * 256;
        const int row = id >> 3, c16 = id & 7;
        const uint32_t doff = SWZ((uint32_t)(row * 128 + c16 * 16));
        const size_t so = (size_t)row * aStr + kt + c16 * 8;
        cp16(stageU32 + doff,          Ahi + so);
        cp16(stageU32 + 16384 + doff,  Alo + so);
        const size_t sb = (size_t)row * bStr + kt + c16 * 8;
        cp16(stageU32 + 32768 + doff,  Bhi + sb);
        cp16(stageU32 + 49152 + doff,  Blo + sb);
    }
}

// Compute one 64-wide k-chunk into acc[4][4][4] (3 split passes).
__device__ __forceinline__ void stage_compute(uint32_t stageU32, int wid, int lane,
                                              float acc[4][4][4])
{
    const int warp_row = wid >> 2;        // 0..1 -> M offset *64
    const int warp_col = wid & 3;         // 0..3 -> N offset *32
    const int lrow = lane & 15;
    const int chalf = (lane >= 16) ? 16 : 0;

#pragma unroll
    for (int ks = 0; ks < 4; ks++) {
        const uint32_t bcol = ks * 32 + chalf;
        uint32_t ahi[4][4], alo[4][4];
#pragma unroll
        for (int mi = 0; mi < 4; mi++) {
            const uint32_t off = SWZ((uint32_t)((warp_row * 64 + mi * 16 + lrow) * 128 + bcol));
            ldsm4(ahi[mi], stageU32 + off);
            ldsm4(alo[mi], stageU32 + 16384 + off);
        }
        uint32_t bhi[2][4], blo[2][4];
#pragma unroll
        for (int nh = 0; nh < 2; nh++) {
            const uint32_t off = SWZ((uint32_t)((warp_col * 32 + nh * 16 + lrow) * 128 + bcol));
            ldsm4(bhi[nh], stageU32 + 32768 + off);
            ldsm4(blo[nh], stageU32 + 49152 + off);
        }
#pragma unroll
        for (int mi = 0; mi < 4; mi++)
#pragma unroll
            for (int ni = 0; ni < 4; ni++) {
                const int nh = ni >> 1, s = ni & 1;
                mma_bf16(acc[mi][ni], ahi[mi], bhi[nh][s], bhi[nh][s + 2]);
                mma_bf16(acc[mi][ni], alo[mi], bhi[nh][s], bhi[nh][s + 2]);
                mma_bf16(acc[mi][ni], ahi[mi], blo[nh][s], blo[nh][s + 2]);
            }
    }
}

// Pipelined K loop shared by both MMA kernels.
template <int KCHUNKS>
__device__ __forceinline__ void mma_mainloop(
    const __nv_bfloat16* Ahi, const __nv_bfloat16* Alo, size_t aStr,
    const __nv_bfloat16* Bhi, const __nv_bfloat16* Blo, size_t bStr,
    uint32_t smemU32, int t, int wid, int lane, float acc[4][4][4])
{
    stage_load(Ahi, Alo, aStr, Bhi, Blo, bStr, 0, smemU32, t);
    cp_commit();
    for (int c = 0; c < KCHUNKS; c++) {
        const bool more = (c + 1) < KCHUNKS;
        if (more) {
            stage_load(Ahi, Alo, aStr, Bhi, Blo, bStr, (c + 1) * 64,
                       smemU32 + ((c + 1) & 1) * STG, t);
            cp_commit();
            asm volatile("cp.async.wait_group 1;" ::: "memory");
        } else {
            asm volatile("cp.async.wait_group 0;" ::: "memory");
        }
        __syncthreads();
        stage_compute(smemU32 + (c & 1) * STG, wid, lane, acc);
        __syncthreads();
    }
}

// ============================================================================
// Energy: E[b][i][j] = sum_d q[i][d] k[j][d].   M = i tile, N = j tile, K=128.
// ============================================================================
__global__ void __launch_bounds__(256, 1)
mma_energy(const __nv_bfloat16* __restrict__ qhi, const __nv_bfloat16* __restrict__ qlo,
           const __nv_bfloat16* __restrict__ khi, const __nv_bfloat16* __restrict__ klo,
           float* __restrict__ E)
{
    extern __shared__ char smem[];
    const uint32_t smemU32 = smem_to_u32(smem);
    const int t = threadIdx.x, wid = t >> 5, lane = t & 31;
    const int b = blockIdx.z;
    const int i0 = blockIdx.y * 128, j0 = blockIdx.x * 128;

    const size_t aoff = ((size_t)b * NN + i0) * DD;
    const size_t boff = ((size_t)b * NN + j0) * DD;

    float acc[4][4][4] = {};
    mma_mainloop<2>(qhi + aoff, qlo + aoff, DD, khi + boff, klo + boff, DD,
                    smemU32, t, wid, lane, acc);

    float* Eb = E + (size_t)b * NN * NN;
    const int rbase = i0 + (wid >> 2) * 64 + (lane >> 2);
    const int cbase = j0 + (wid & 3) * 32 + (lane & 3) * 2;
#pragma unroll
    for (int mi = 0; mi < 4; mi++)
#pragma unroll
        for (int ni = 0; ni < 4; ni++) {
            const int r = rbase + mi * 16;
            const int cjj = cbase + ni * 8;
            *(float2*)&Eb[(size_t)r * NN + cjj]       = make_float2(acc[mi][ni][0], acc[mi][ni][1]);
            *(float2*)&Eb[(size_t)(r + 8) * NN + cjj] = make_float2(acc[mi][ni][2], acc[mi][ni][3]);
        }
}

// ============================================================================
// Out: out[b][c][i] = g * (sum_j v[c][j] p[i][j]) * inv[i] + x[c][i].
// M = c tile (A = v rows), N = i tile (B = p rows), K = 4096.
// ============================================================================
__global__ void __launch_bounds__(256, 1)
mma_out(const __nv_bfloat16* __restrict__ vhi, const __nv_bfloat16* __restrict__ vlo,
        const __nv_bfloat16* __restrict__ phi, const __nv_bfloat16* __restrict__ plo,
        const float* __restrict__ X, const float* __restrict__ gamma,
        const float* __restrict__ invs, float* __restrict__ Out)
{
    extern __shared__ char smem[];
    const uint32_t smemU32 = smem_to_u32(smem);
    const int t = threadIdx.x, wid = t >> 5, lane = t & 31;
    const int b = blockIdx.z;
    const int c0 = blockIdx.x * 128, i0 = blockIdx.y * 128;

    const size_t aoff = ((size_t)b * CC + c0) * NN;
    const size_t boff = ((size_t)b * NN + i0) * NN;

    float acc[4][4][4] = {};
    mma_mainloop<64>(vhi + aoff, vlo + aoff, NN, phi + boff, plo + boff, NN,
                     smemU32, t, wid, lane, acc);

    const float g = __ldg(gamma);
    const int rbase = c0 + (wid >> 2) * 64 + (lane >> 2);
    const int cbase = i0 + (wid & 3) * 32 + (lane & 3) * 2;
    const float* ivb = invs + b * NN;
#pragma unroll
    for (int mi = 0; mi < 4; mi++)
#pragma unroll
        for (int ni = 0; ni < 4; ni++) {
            const int ch = rbase + mi * 16;
            const int ci = cbase + ni * 8;
            const float2 iv = *(const float2*)&ivb[ci];
            {
                const size_t idx = ((size_t)b * CC + ch) * NN + ci;
                const float2 xv = *(const float2*)&X[idx];
                float2 o;
                o.x = g * acc[mi][ni][0] * iv.x + xv.x;
                o.y = g * acc[mi][ni][1] * iv.y + xv.y;
                *(float2*)&Out[idx] = o;
            }
            {
                const size_t idx = ((size_t)b * CC + ch + 8) * NN + ci;
                const float2 xv = *(const float2*)&X[idx];
                float2 o;
                o.x = g * acc[mi][ni][2] * iv.x + xv.x;
                o.y = g * acc[mi][ni][3] * iv.y + xv.y;
                *(float2*)&Out[idx] = o;
            }
        }
}

// ============================================================================
// fp32 proj SGEMM machinery (verified R3) with bf16 split epilogues
// ============================================================================
__device__ __forceinline__ void mm_step(const float* __restrict__ As,
                                        const float* __restrict__ Bs,
                                        int tx, int ty, float acc[8][8])
{
#pragma unroll
    for (int kk = 0; kk < 16; kk++) {
        float a[8], b[8];
        *(float4*)&a[0] = *(const float4*)&As[kk * 128 + ty * 4];
        *(float4*)&a[4] = *(const float4*)&As[kk * 128 + 64 + ty * 4];
        *(float4*)&b[0] = *(const float4*)&Bs[kk * 128 + tx * 4];
        *(float4*)&b[4] = *(const float4*)&Bs[kk * 128 + 64 + tx * 4];
#pragma unroll
        for (int i = 0; i < 8; i++)
#pragma unroll
            for (int j = 0; j < 8; j++)
                acc[i][j] += a[i] * b[j];
    }
}

__global__ void __launch_bounds__(256, 2)
gemm_nn_v(const float* __restrict__ W, const float* __restrict__ bias,
          const float* __restrict__ X,
          __nv_bfloat16* __restrict__ Vhi, __nv_bfloat16* __restrict__ Vlo)
{
    __shared__ float As[2][16 * 128], Bs[2][16 * 128];
    const int b = blockIdx.z;
    const float* Xb = X + (size_t)b * CC * NN;
    const int m0 = blockIdx.y * 128;
    const int n0 = blockIdx.x * 128;
    const int t = threadIdx.x;
    const int tx = t & 15, ty = t >> 4;

    const int aM = t & 127, aK = (t >> 7) * 8;
    const int bK = t >> 4,  bN = (t & 15) * 8;

    float4 ra0, ra1, rb0, rb1;
    float acc[8][8] = {};

    auto ldg = [&](int kt) {
        const float* pa = &W[(size_t)(m0 + aM) * CC + kt + aK];
        ra0 = *(const float4*)pa; ra1 = *(const float4*)(pa + 4);
        const float* pb = &Xb[(size_t)(kt + bK) * NN + n0 + bN];
        rb0 = *(const float4*)pb; rb1 = *(const float4*)(pb + 4);
    };
    auto sts = [&](int buf) {
        float* a = As[buf];
        a[(aK + 0) * 128 + aM] = ra0.x; a[(aK + 1) * 128 + aM] = ra0.y;
        a[(aK + 2) * 128 + aM] = ra0.z; a[(aK + 3) * 128 + aM] = ra0.w;
        a[(aK + 4) * 128 + aM] = ra1.x; a[(aK + 5) * 128 + aM] = ra1.y;
        a[(aK + 6) * 128 + aM] = ra1.z; a[(aK + 7) * 128 + aM] = ra1.w;
        float* bb = Bs[buf];
        *(float4*)&bb[bK * 128 + bN] = rb0;
        *(float4*)&bb[bK * 128 + bN + 4] = rb1;
    };

    ldg(0); sts(0); __syncthreads();
    int buf = 0;
    for (int kt = 0; kt < CC; kt += 16) {
        const bool more = (kt + 16) < CC;
        if (more) ldg(kt + 16);
        mm_step(As[buf], Bs[buf], tx, ty, acc);
        if (more) { sts(buf ^ 1); __syncthreads(); buf ^= 1; }
    }

#pragma unroll
    for (int i = 0; i < 8; i++) {
        const int m = m0 + ((i < 4) ? ty * 4 + i : 64 + ty * 4 + i - 4);
        const float bi = bias[m];
        const size_t rb = ((size_t)b * CC + m) * NN;
        float f[4];
        __nv_bfloat16 h[4], l[4];
        f[0] = acc[i][0] + bi; f[1] = acc[i][1] + bi; f[2] = acc[i][2] + bi; f[3] = acc[i][3] + bi;
        split4(f, h, l);
        *(uint2*)&Vhi[rb + n0 + tx * 4] = *(uint2*)h;
        *(uint2*)&Vlo[rb + n0 + tx * 4] = *(uint2*)l;
        f[0] = acc[i][4] + bi; f[1] = acc[i][5] + bi; f[2] = acc[i][6] + bi; f[3] = acc[i][7] + bi;
        split4(f, h, l);
        *(uint2*)&Vhi[rb + n0 + 64 + tx * 4] = *(uint2*)h;
        *(uint2*)&Vlo[rb + n0 + 64 + tx * 4] = *(uint2*)l;
    }
}

// dual q/k projection: transposed bf16 split epilogue -> [b][n][128] (+d_off)
__global__ void __launch_bounds__(256, 2)
gemm_nn_dual(const float* __restrict__ W0, const float* __restrict__ W1,
             const float* __restrict__ bias0, const float* __restrict__ bias1,
             const float* __restrict__ X,
             __nv_bfloat16* __restrict__ Qhi, __nv_bfloat16* __restrict__ Qlo,
             __nv_bfloat16* __restrict__ Khi, __nv_bfloat16* __restrict__ Klo,
             int d_off)
{
    __shared__ float As[2][16 * 128], Bs[2][16 * 128];
    const int b = blockIdx.z;
    const float* Xb = X + (size_t)b * CC * NN;
    const int n0 = blockIdx.x * 128;
    const int t = threadIdx.x;
    const int tx = t & 15, ty = t >> 4;

    const int aM = t & 127, aK = (t >> 7) * 8;
    const int bK = t >> 4,  bN = (t & 15) * 8;
    const float* Wrow = (aM < CQ) ? (W0 + (size_t)aM * CC)
                                  : (W1 + (size_t)(aM - CQ) * CC);

    float4 ra0, ra1, rb0, rb1;
    float acc[8][8] = {};

    auto ldg = [&](int kt) {
        const float* pa = Wrow + kt + aK;
        ra0 = *(const float4*)pa; ra1 = *(const float4*)(pa + 4);
        const float* pb = &Xb[(size_t)(kt + bK) * NN + n0 + bN];
        rb0 = *(const float4*)pb; rb1 = *(const float4*)(pb + 4);
    };
    auto sts = [&](int buf) {
        float* a = As[buf];
        a[(aK + 0) * 128 + aM] = ra0.x; a[(aK + 1) * 128 + aM] = ra0.y;
        a[(aK + 2) * 128 + aM] = ra0.z; a[(aK + 3) * 128 + aM] = ra0.w;
        a[(aK + 4) * 128 + aM] = ra1.x; a[(aK + 5) * 128 + aM] = ra1.y;
        a[(aK + 6) * 128 + aM] = ra1.z; a[(aK + 7) * 128 + aM] = ra1.w;
        float* bb = Bs[buf];
        *(float4*)&bb[bK * 128 + bN] = rb0;
        *(float4*)&bb[bK * 128 + bN + 4] = rb1;
    };

    ldg(0); sts(0); __syncthreads();
    int buf = 0;
    for (int kt = 0; kt < CC; kt += 16) {
        const bool more = (kt + 16) < CC;
        if (more) ldg(kt + 16);
        mm_step(As[buf], Bs[buf], tx, ty, acc);
        if (more) { sts(buf ^ 1); __syncthreads(); buf ^= 1; }
    }

    float bq[4], bk2[4];
#pragma unroll
    for (int i = 0; i < 4; i++) { bq[i] = bias0[ty * 4 + i]; bk2[i] = bias1[ty * 4 + i]; }

#pragma unroll
    for (int j = 0; j < 8; j++) {
        const int nj = n0 + ((j < 4) ? tx * 4 + j : 64 + tx * 4 + j - 4);
        const size_t rowQ = ((size_t)b * NN + nj) * DD + d_off + ty * 4;
        float f[4];
        __nv_bfloat16 h[4], l[4];
#pragma unroll
        for (int i = 0; i < 4; i++) f[i] = acc[i][j] + bq[i];
        split4(f, h, l);
        *(uint2*)&Qhi[rowQ] = *(uint2*)h;
        *(uint2*)&Qlo[rowQ] = *(uint2*)l;
#pragma unroll
        for (int i = 0; i < 4; i++) f[i] = acc[4 + i][j] + bk2[i];
        split4(f, h, l);
        *(uint2*)&Khi[rowQ] = *(uint2*)h;
        *(uint2*)&Klo[rowQ] = *(uint2*)l;
    }
}

// ============================================================================
// Softmax: fp32 energy row -> unnormalized exp bf16 hi/lo + 1/rowsum
// ============================================================================
__global__ void __launch_bounds__(256)
softmax_rows(const float* __restrict__ E,
             __nv_bfloat16* __restrict__ Phi, __nv_bfloat16* __restrict__ Plo,
             float* __restrict__ invs)
{
    __shared__ float red[8];
    const float4* E4 = (const float4*)E;
    const size_t base4 = (size_t)blockIdx.x * (NN / 4);
    const int tid = threadIdx.x;
    const int lane = tid & 31, wid = tid >> 5;

    float4 v[4];
#pragma unroll
    for (int u = 0; u < 4; u++) v[u] = E4[base4 + u * 256 + tid];

    float m = -1e30f;
#pragma unroll
    for (int u = 0; u < 4; u++)
        m = fmaxf(m, fmaxf(fmaxf(v[u].x, v[u].y), fmaxf(v[u].z, v[u].w)));
#pragma unroll
    for (int off = 16; off > 0; off >>= 1)
        m = fmaxf(m, __shfl_xor_sync(0xffffffffu, m, off));
    if (lane == 0) red[wid] = m;
    __syncthreads();
    m = red[0];
#pragma unroll
    for (int w = 1; w < 8; w++) m = fmaxf(m, red[w]);
    __syncthreads();

    float s = 0.f;
#pragma unroll
    for (int u = 0; u < 4; u++) {
        v[u].x = __expf(v[u].x - m); v[u].y = __expf(v[u].y - m);
        v[u].z = __expf(v[u].z - m); v[u].w = __expf(v[u].w - m);
        s += v[u].x + v[u].y + v[u].z + v[u].w;
    }
#pragma unroll
    for (int off = 16; off > 0; off >>= 1)
        s += __shfl_xor_sync(0xffffffffu, s, off);
    if (lane == 0) red[wid] = s;
    __syncthreads();
    s = red[0];
#pragma unroll
    for (int w = 1; w < 8; w++) s += red[w];

#pragma unroll
    for (int u = 0; u < 4; u++) {
        const size_t el = base4 * 4 + (u * 256 + tid) * 4;
        float f[4] = { v[u].x, v[u].y, v[u].z, v[u].w };
        __nv_bfloat16 h[4], l[4];
        split4(f, h, l);
        *(uint2*)&Phi[el] = *(uint2*)h;
        *(uint2*)&Plo[el] = *(uint2*)l;
    }
    if (tid == 0) invs[blockIdx.x] = 1.0f / s;
}

// ============================================================================

extern "C" void kernel_launch(void* const* d_in, const int* in_sizes, int n_in,
                              void* d_out, int out_size)
{
    const float* x     = (const float*)d_in[0];
    const float* dep   = (const float*)d_in[1];
    const float* wq    = (const float*)d_in[2];
    const float* bq    = (const float*)d_in[3];
    const float* wqd   = (const float*)d_in[4];
    const float* bqd   = (const float*)d_in[5];
    const float* wk    = (const float*)d_in[6];
    const float* bk    = (const float*)d_in[7];
    const float* wkd   = (const float*)d_in[8];
    const float* bkd   = (const float*)d_in[9];
    const float* wv    = (const float*)d_in[10];
    const float* bv    = (const float*)d_in[11];
    const float* gamma = (const float*)d_in[12];
    float* out = (float*)d_out;

    __nv_bfloat16 *qhi, *qlo, *khi, *klo, *vhi, *vlo, *phi, *plo;
    float *e, *s;
    cudaGetSymbolAddress((void**)&qhi, g_qhi);
    cudaGetSymbolAddress((void**)&qlo, g_qlo);
    cudaGetSymbolAddress((void**)&khi, g_khi);
    cudaGetSymbolAddress((void**)&klo, g_klo);
    cudaGetSymbolAddress((void**)&vhi, g_vhi);
    cudaGetSymbolAddress((void**)&vlo, g_vlo);
    cudaGetSymbolAddress((void**)&phi, g_phi);
    cudaGetSymbolAddress((void**)&plo, g_plo);
    cudaGetSymbolAddress((void**)&e, g_e);
    cudaGetSymbolAddress((void**)&s, g_s);

    cudaFuncSetAttribute(mma_energy, cudaFuncAttributeMaxDynamicSharedMemorySize, MMA_SMEM_BYTES);
    cudaFuncSetAttribute(mma_out,    cudaFuncAttributeMaxDynamicSharedMemorySize, MMA_SMEM_BYTES);

    // q/k projections: x -> d [0:64), dep -> d [64:128)  (layout [b][n][128])
    gemm_nn_dual<<<dim3(NN / 128, 1, BB), 256>>>(wq,  wk,  bq,  bk,  x,   qhi, qlo, khi, klo, 0);
    gemm_nn_dual<<<dim3(NN / 128, 1, BB), 256>>>(wqd, wkd, bqd, bkd, dep, qhi, qlo, khi, klo, CQ);

    // v projection -> bf16 hi/lo
    gemm_nn_v<<<dim3(NN / 128, CC / 128, BB), 256>>>(wv, bv, x, vhi, vlo);

    // energy via warp MMA (split bf16)
    mma_energy<<<dim3(NN / 128, NN / 128, BB), 256, MMA_SMEM_BYTES>>>(qhi, qlo, khi, klo, e);

    // softmax -> exp hi/lo + 1/rowsum
    softmax_rows<<<BB * NN, 256>>>(e, phi, plo, s);

    // out via warp MMA (normalization folded in)
    mma_out<<<dim3(CC / 128, NN / 128, BB), 256, MMA_SMEM_BYTES>>>(vhi, vlo, phi, plo, x, gamma, s, out);
}